// round 15
// baseline (speedup 1.0000x reference)
#include <cuda_runtime.h>
#include <cstdint>
#include <math.h>

#define HIDDEN 2048
#define NH 16
#define NKV 4
#define HD 128
#define BB 2
#define TT 2048
#define MTOT (BB*TT)            // 4096 rows (B*T)
#define QDIM (NH*HD)            // 2048
#define KVDIM (2*NKV*HD)        // 1024

// Scratch (allocation-free)
__device__ float g_Q  [MTOT * QDIM];            // Q proj out: pre-scaled, tf32-rounded
__device__ float g_K2 [BB * NKV * TT * HD];     // K: [b][kvh][t][d], tf32-rounded
__device__ float g_Vt [BB * NKV * HD * TT];     // V^T: [b][kvh][d][t], tf32-rounded
__device__ float g_O  [MTOT * QDIM];            // attention out, tf32-rounded
__device__ float g_xt [MTOT * HIDDEN];          // tf32-rounded inputs
__device__ float g_wqt [QDIM * HIDDEN];
__device__ float g_wkvt[KVDIM * HIDDEN];
__device__ float g_wot [HIDDEN * QDIM];

// Cross-kernel progress flags (reset each launch by cvt_all)
__device__ int g_kv_done[32];   // per 128-row block of QKV proj output; target 24
__device__ int g_at_done[32];   // per 128-row attention q-block (global); target 16

__device__ __forceinline__ uint32_t f2tf(float f) {
    uint32_t u;
    asm("cvt.rna.tf32.f32 %0, %1;" : "=r"(u) : "f"(f));
    return u;
}
__device__ __forceinline__ float f2tff(float f) { return __uint_as_float(f2tf(f)); }

__device__ __forceinline__ void cp16(uint32_t smaddr, const void* g) {
    asm volatile("cp.async.cg.shared.global [%0], [%1], 16;" :: "r"(smaddr), "l"(g));
}
#define CP_COMMIT() asm volatile("cp.async.commit_group;" ::: "memory")

__device__ __forceinline__ uint32_t smem_u32(const void* p) {
    return (uint32_t)__cvta_generic_to_shared(p);
}

__device__ __forceinline__ void ldsm_x4(uint32_t& r0, uint32_t& r1, uint32_t& r2, uint32_t& r3,
                                        uint32_t addr) {
    asm volatile("ldmatrix.sync.aligned.m8n8.x4.shared.b16 {%0,%1,%2,%3}, [%4];"
                 : "=r"(r0), "=r"(r1), "=r"(r2), "=r"(r3) : "r"(addr));
}

__device__ __forceinline__ void mma_tf32(float& d0, float& d1, float& d2, float& d3,
                                         uint32_t a0, uint32_t a1, uint32_t a2, uint32_t a3,
                                         uint32_t b0, uint32_t b1) {
    asm volatile("mma.sync.aligned.m16n8k8.row.col.f32.tf32.tf32.f32 "
                 "{%0,%1,%2,%3}, {%4,%5,%6,%7}, {%8,%9}, {%0,%1,%2,%3};"
                 : "+f"(d0), "+f"(d1), "+f"(d2), "+f"(d3)
                 : "r"(a0), "r"(a1), "r"(a2), "r"(a3), "r"(b0), "r"(b1));
}
__device__ __forceinline__ void mma_tf32a(float* d, const uint32_t* a, uint32_t b0, uint32_t b1) {
    mma_tf32(d[0], d[1], d[2], d[3], a[0], a[1], a[2], a[3], b0, b1);
}

// ---------------------------------------------------------------------------
// Fused tf32-rounding pass over all four inputs + flag reset
// ---------------------------------------------------------------------------
#define N1 (MTOT*HIDDEN/4)
#define N2 (N1 + QDIM*HIDDEN/4)
#define N3 (N2 + KVDIM*HIDDEN/4)
#define N4 (N3 + HIDDEN*QDIM/4)

__global__ void cvt_all(const float4* __restrict__ x,  const float4* __restrict__ wq,
                        const float4* __restrict__ wkv, const float4* __restrict__ wo)
{
    const int i = blockIdx.x * blockDim.x + threadIdx.x;
    if (i < 32) { g_kv_done[i] = 0; g_at_done[i] = 0; }

    const float4* src; float4* dst; int j;
    if (i < N1)      { src = x;   dst = (float4*)g_xt;   j = i; }
    else if (i < N2) { src = wq;  dst = (float4*)g_wqt;  j = i - N1; }
    else if (i < N3) { src = wkv; dst = (float4*)g_wkvt; j = i - N2; }
    else if (i < N4) { src = wo;  dst = (float4*)g_wot;  j = i - N3; }
    else return;
    float4 v = src[j];
    dst[j] = make_float4(f2tff(v.x), f2tff(v.y), f2tff(v.z), f2tff(v.w));
}

// ---------------------------------------------------------------------------
// TF32 mma.sync GEMM with cp.async pipeline.
// mode 0: plain fp32 store to C
// mode 1: Q — store f2tf(scale * v) to C (=g_Q)
// mode 2: KV — scatter K to g_K2 [b][kvh][t][d], V to g_Vt [b][kvh][d][t], tf32
// ---------------------------------------------------------------------------
#define LDA 20
#define NSTAGE 4
#define STG_W (128 * LDA)
#define GEMM_SMEM (NSTAGE * 2 * STG_W * 4)   // 81920 B

__device__ __forceinline__ void epi_kv(int rg, int col, float x, float y)
{
    const int b = rg >> 11, t = rg & (TT - 1);
    if (col < NKV * HD) {
        const int kvh = col >> 7, d = col & 127;
        *(float2*)(g_K2 + ((size_t)((b * NKV + kvh) * TT + t)) * HD + d) =
            make_float2(f2tff(x), f2tff(y));
    } else {
        const int c2 = col - NKV * HD;
        const int kvh = c2 >> 7, d = c2 & 127;
        float* base = g_Vt + ((size_t)(b * NKV + kvh) * HD + d) * TT + t;
        base[0]  = f2tff(x);
        base[TT] = f2tff(y);
    }
}

__device__ __forceinline__ void gemm_core(const float* __restrict__ A,
                                          const float* __restrict__ B,
                                          float* __restrict__ C,
                                          int bm, int bn, int N, int K, int mode)
{
    extern __shared__ uint32_t smg[];
    uint32_t* sA = smg;
    uint32_t* sB = smg + NSTAGE * STG_W;

    const int tid  = threadIdx.x;
    const int lane = tid & 31;
    const int wid  = tid >> 5;
    const int wm   = wid & 1;
    const int wn   = wid >> 1;

    const int grow  = tid >> 2;
    const int gcol4 = tid & 3;

    const int gA = lane >> 3;
    const int a_row   = (lane & 7) | ((gA & 1) << 3);
    const int a_chunk = (gA >> 1) * 4;
    const int b_row   = (lane & 7) | (((lane >> 3) >> 1) << 3);
    const int b_chunk = ((lane >> 3) & 1) * 4;

    const uint32_t sAb = smem_u32(sA);
    const uint32_t sBb = smem_u32(sB);

    const float* Ar = A + (size_t)(bm + grow) * K + gcol4 * 4;
    const float* Br = B + (size_t)(bn + grow) * K + gcol4 * 4;
    const uint32_t doff = 4u * (grow * LDA + gcol4 * 4);

    float c[4][4][4];
#pragma unroll
    for (int mi = 0; mi < 4; mi++)
#pragma unroll
        for (int ni = 0; ni < 4; ni++)
#pragma unroll
            for (int r = 0; r < 4; r++) c[mi][ni][r] = 0.f;

    const int NKT = K / 16;

    auto issue = [&](int kt) {
        const int s = kt & (NSTAGE - 1);
        const uint32_t sb = 4u * (s * STG_W);
        const int koff = kt * 16;
        cp16(sAb + sb + doff,                 Ar + koff);
        cp16(sAb + sb + doff + 4u * 64 * LDA, Ar + koff + (size_t)64 * K);
        cp16(sBb + sb + doff,                 Br + koff);
        cp16(sBb + sb + doff + 4u * 64 * LDA, Br + koff + (size_t)64 * K);
    };

    issue(0); CP_COMMIT();
    issue(1); CP_COMMIT();
    issue(2); CP_COMMIT();

    for (int kt = 0; kt < NKT; kt++) {
        asm volatile("cp.async.wait_group 2;" ::: "memory");
        __syncthreads();

        if (kt + 3 < NKT) issue(kt + 3);
        CP_COMMIT();

        const int cur = kt & (NSTAGE - 1);
        const uint32_t baseA = sAb + 4u * (cur * STG_W);
        const uint32_t baseB = sBb + 4u * (cur * STG_W);
#pragma unroll
        for (int ks = 0; ks < 2; ks++) {
            uint32_t a[4][4];
#pragma unroll
            for (int mi = 0; mi < 4; mi++) {
                uint32_t addr = baseA + 4u * ((wm * 64 + mi * 16 + a_row) * LDA + ks * 8 + a_chunk);
                ldsm_x4(a[mi][0], a[mi][1], a[mi][2], a[mi][3], addr);
            }
            uint32_t b[2][4];
#pragma unroll
            for (int p = 0; p < 2; p++) {
                uint32_t addr = baseB + 4u * ((wn * 32 + p * 16 + b_row) * LDA + ks * 8 + b_chunk);
                ldsm_x4(b[p][0], b[p][1], b[p][2], b[p][3], addr);
            }
#pragma unroll
            for (int mi = 0; mi < 4; mi++) {
#pragma unroll
                for (int p = 0; p < 2; p++) {
                    mma_tf32a(c[mi][2*p+0], a[mi], b[p][0], b[p][1]);
                    mma_tf32a(c[mi][2*p+1], a[mi], b[p][2], b[p][3]);
                }
            }
        }
    }

    const float qscale = 0.08838834764831845f;   // 1/sqrt(128)
#pragma unroll
    for (int mi = 0; mi < 4; mi++) {
        int rg = bm + wm * 64 + mi * 16 + (lane >> 2);
#pragma unroll
        for (int ni = 0; ni < 4; ni++) {
            int col = bn + wn * 32 + ni * 8 + (lane & 3) * 2;
            if (mode == 0) {
                *(float2*)(C + (size_t)rg * N + col)       = make_float2(c[mi][ni][0], c[mi][ni][1]);
                *(float2*)(C + (size_t)(rg + 8) * N + col) = make_float2(c[mi][ni][2], c[mi][ni][3]);
            } else if (mode == 1) {
                *(float2*)(C + (size_t)rg * N + col) =
                    make_float2(f2tff(qscale * c[mi][ni][0]), f2tff(qscale * c[mi][ni][1]));
                *(float2*)(C + (size_t)(rg + 8) * N + col) =
                    make_float2(f2tff(qscale * c[mi][ni][2]), f2tff(qscale * c[mi][ni][3]));
            } else {
                epi_kv(rg,     col, c[mi][ni][0], c[mi][ni][1]);
                epi_kv(rg + 8, col, c[mi][ni][2], c[mi][ni][3]);
            }
        }
    }
}

__global__ __launch_bounds__(256, 2) void gemm_qkv(const float* __restrict__ xt,
                                                   const float* __restrict__ wqt,
                                                   const float* __restrict__ wkvt)
{
#if __CUDA_ARCH__ >= 900
    cudaTriggerProgrammaticLaunchCompletion();
#endif
    const int bx = blockIdx.x;
    const int bm = blockIdx.y * 128;
    if (bx < QDIM / 128)
        gemm_core(xt, wqt, g_Q, bm, bx * 128, QDIM, HIDDEN, 1);
    else
        gemm_core(xt, wkvt, nullptr, bm, (bx - QDIM / 128) * 128, KVDIM, HIDDEN, 2);

    // release: this (bm, bn-tile) is complete
    __threadfence();
    __syncthreads();
    if (threadIdx.x == 0) atomicAdd(&g_kv_done[blockIdx.y], 1);
}

__global__ __launch_bounds__(256, 2) void gemm_o(const float* __restrict__ A,
                                                 const float* __restrict__ B,
                                                 float* __restrict__ C)
{
    // acquire: need attention q-block `by` complete (16 heads)
    if (threadIdx.x == 0) {
        while (((volatile int*)g_at_done)[blockIdx.y] < 16) __nanosleep(64);
    }
    __syncthreads();
    gemm_core(A, B, C, blockIdx.y * 128, blockIdx.x * 128, QDIM, HIDDEN, 0);
}

// ---------------------------------------------------------------------------
// Flash attention (causal, GQA), tf32 mma.sync, fully cp.async-fed.
// BLOCK_M=128 (8 warps, 256 threads), BLOCK_N=64.
// K double-buffered; V^T single-buffered, wait deferred past softmax.
// P ALIASES the just-consumed K stage (t&1): K(t) dead after S-ldsm (sync),
// P(t) dead before fill_K(t+2) re-targets that stage (loop-top sync).
// P layout: 256B rows with XOR-chunk swizzle -> conflict-free STS + ldsm.
// Smem 96KB -> 2 CTAs/SM (16 warps/SM).
// ---------------------------------------------------------------------------
#define K_STAGE_B 32768                 // 64 keys x 512B
#define VT_B      32768                 // 128 d x 256B
#define ATTN_SMEM (2 * K_STAGE_B + VT_B)   // 98304

__global__ __launch_bounds__(256, 2) void attn_mma(const float* __restrict__ Q,
                                                   float* __restrict__ O)
{
#if __CUDA_ARCH__ >= 900
    cudaTriggerProgrammaticLaunchCompletion();
#endif
    extern __shared__ uint8_t smb[];
    const uint32_t sK0 = smem_u32(smb);
    const uint32_t sVt = sK0 + 2 * K_STAGE_B;

    const int bh  = blockIdx.y;
    const int b   = bh / NH;
    const int h   = bh % NH;
    const int kvh = h / (NH / NKV);
    const int qm  = blockIdx.x * 128;          // ascending: aligns with producer order

    const int tid  = threadIdx.x;
    const int w    = tid >> 5;                 // 0..7
    const int lane = tid & 31;
    const int g    = lane >> 3;
    const int q4   = lane & 3;
    const int hr   = lane >> 2;
    const int a_row   = (lane & 7) | ((g & 1) << 3);
    const int a_csel  = (g >> 1);                   // A-frag 16B-chunk select (0/1) within k-step
    const int b_row   = (lane & 7) | ((g >> 1) << 3);
    const int b_sub   = (g & 1);                    // 16B sub-chunk within k-step

    // acquire: need QKV row-blocks b*16 .. b*16 + qm/128 complete
    if (tid == 0) {
        const int kb_hi = b * 16 + (qm >> 7);
        for (int kb = b * 16; kb <= kb_hi; kb++)
            while (((volatile int*)g_kv_done)[kb] < 24) __nanosleep(64);
    }
    __syncthreads();

    const int r0 = qm + 16 * w + hr;
    const int r1 = r0 + 8;

    const float* Kg = g_K2 + (size_t)(b * NKV + kvh) * TT * HD;
    const float* Vg = g_Vt + (size_t)(b * NKV + kvh) * HD * TT;

    // cp.async fill mappings (256 threads)
    const int kr = tid >> 5;   // K: rows kr+8j (j<8), chunk kc (32 per 512B row)
    const int kc = tid & 31;
    const int vd = tid >> 4;   // V: d-rows vd+16j (j<8), chunk vc (16 per 256B row)
    const int vc = tid & 15;

    auto fill_K = [&](int t, int stage) {
        const uint32_t dstb = sK0 + stage * K_STAGE_B;
        const float* src = Kg + (size_t)(t * 64 + kr) * HD + kc * 4;
#pragma unroll
        for (int j = 0; j < 8; j++) {
            const int r = kr + 8 * j;
            cp16(dstb + r * 512 + ((kc ^ (r & 7)) << 4), src + (size_t)(8 * j) * HD);
        }
    };
    auto fill_V = [&](int t) {
        const float* src = Vg + (size_t)vd * TT + t * 64 + vc * 4;
#pragma unroll
        for (int j = 0; j < 8; j++) {
            const int d = vd + 16 * j;
            cp16(sVt + d * 256 + ((vc ^ (d & 7)) << 4), src + (size_t)(16 * j) * TT);
        }
    };

    // prefetch K tile 0, then load Q fragments (pre-scaled, pre-rounded)
    fill_K(0, 0);
    CP_COMMIT();

    uint32_t qf[16][4];
    {
        const uint32_t* Q0 = (const uint32_t*)(Q + ((size_t)(b * TT) + r0) * QDIM + h * HD);
        const uint32_t* Q1 = (const uint32_t*)(Q + ((size_t)(b * TT) + r1) * QDIM + h * HD);
#pragma unroll
        for (int ks = 0; ks < 16; ks++) {
            qf[ks][0] = Q0[8 * ks + q4];
            qf[ks][1] = Q1[8 * ks + q4];
            qf[ks][2] = Q0[8 * ks + q4 + 4];
            qf[ks][3] = Q1[8 * ks + q4 + 4];
        }
    }

    float o[16][4];
#pragma unroll
    for (int i = 0; i < 16; i++)
#pragma unroll
        for (int r = 0; r < 4; r++) o[i][r] = 0.f;
    float m0 = -INFINITY, m1 = -INFINITY, l0 = 0.f, l1 = 0.f;

    const int ntiles = qm / 64 + 2;            // kv tiles 0 .. qm/64+1
    for (int t = 0; t < ntiles; t++) {
        const int n0 = t * 64;
        __syncthreads();                       // old V / P / K-stage dead across CTA

        fill_V(t);
        CP_COMMIT();                           // group V(t)
        if (t + 1 < ntiles) fill_K(t + 1, (t + 1) & 1);
        CP_COMMIT();                           // group K(t+1) (possibly empty)

        asm volatile("cp.async.wait_group 2;" ::: "memory");   // K(t) arrived
        __syncthreads();

        // S = Q K^T
        const uint32_t sKst = sK0 + (t & 1) * K_STAGE_B;
        float s[8][4];
#pragma unroll
        for (int j = 0; j < 8; j++)
#pragma unroll
            for (int r = 0; r < 4; r++) s[j][r] = 0.f;
#pragma unroll
        for (int ks = 0; ks < 16; ks++) {
            uint32_t kb[4][4];
#pragma unroll
            for (int jj = 0; jj < 4; jj++) {
                const int r = 16 * jj + b_row;
                const int cc = 2 * ks + b_sub;
                ldsm_x4(kb[jj][0], kb[jj][1], kb[jj][2], kb[jj][3],
                        sKst + r * 512 + ((cc ^ (r & 7)) << 4));
            }
#pragma unroll
            for (int jj = 0; jj < 4; jj++) {
                mma_tf32a(s[2 * jj + 0], qf[ks], kb[jj][0], kb[jj][1]);
                mma_tf32a(s[2 * jj + 1], qf[ks], kb[jj][2], kb[jj][3]);
            }
        }

        // causal mask + online softmax
        float mt0 = -INFINITY, mt1 = -INFINITY;
#pragma unroll
        for (int j = 0; j < 8; j++) {
            const int c0 = n0 + 8 * j + 2 * q4, c1 = c0 + 1;
            if (c0 > r0) s[j][0] = -1e30f;
            if (c1 > r0) s[j][1] = -1e30f;
            if (c0 > r1) s[j][2] = -1e30f;
            if (c1 > r1) s[j][3] = -1e30f;
            mt0 = fmaxf(mt0, fmaxf(s[j][0], s[j][1]));
            mt1 = fmaxf(mt1, fmaxf(s[j][2], s[j][3]));
        }
        mt0 = fmaxf(mt0, __shfl_xor_sync(0xffffffffu, mt0, 1));
        mt0 = fmaxf(mt0, __shfl_xor_sync(0xffffffffu, mt0, 2));
        mt1 = fmaxf(mt1, __shfl_xor_sync(0xffffffffu, mt1, 1));
        mt1 = fmaxf(mt1, __shfl_xor_sync(0xffffffffu, mt1, 2));
        const float mn0 = fmaxf(m0, mt0), mn1 = fmaxf(m1, mt1);
        const float al0 = __expf(m0 - mn0), al1 = __expf(m1 - mn1);
        m0 = mn0; m1 = mn1;
        float ls0 = 0.f, ls1 = 0.f;
#pragma unroll
        for (int j = 0; j < 8; j++) {
            s[j][0] = __expf(s[j][0] - mn0); ls0 += s[j][0];
            s[j][1] = __expf(s[j][1] - mn0); ls0 += s[j][1];
            s[j][2] = __expf(s[j][2] - mn1); ls1 += s[j][2];
            s[j][3] = __expf(s[j][3] - mn1); ls1 += s[j][3];
        }
        l0 = l0 * al0 + ls0;
        l1 = l1 * al1 + ls1;
#pragma unroll
        for (int i = 0; i < 16; i++) {
            o[i][0] *= al0; o[i][1] *= al0;
            o[i][2] *= al1; o[i][3] *= al1;
        }

        // All warps done ldsm-reading K(t) -> its stage becomes the P buffer
        __syncthreads();
        const uint32_t sPt = sKst;   // P aliases K stage (t&1)
        uint8_t* Pb = smb + (t & 1) * K_STAGE_B;

        // P (tf32) -> swizzled smem: row stride 256B, chunk ^= (row&7)
        {
            const int prow = 16 * w + hr;
            const int wi = (q4 & 1) * 8;               // byte offset within 16B chunk
#pragma unroll
            for (int j = 0; j < 8; j++) {
                const int ch = 2 * j + (q4 >> 1);
                *(uint2*)(Pb + prow * 256 + ((ch ^ (prow & 7)) << 4) + wi) =
                    make_uint2(f2tf(s[j][0]), f2tf(s[j][1]));
                const int pr1 = prow + 8;
                *(uint2*)(Pb + pr1 * 256 + ((ch ^ (pr1 & 7)) << 4) + wi) =
                    make_uint2(f2tf(s[j][2]), f2tf(s[j][3]));
            }
        }
        __syncwarp();

        asm volatile("cp.async.wait_group 1;" ::: "memory");   // V(t) arrived
        __syncthreads();

        // O += P V  (A-frags from swizzled P, B-frags from V^T smem)
#pragma unroll
        for (int ks = 0; ks < 8; ks++) {
            const int pr = 16 * w + a_row;
            const int pch = 2 * ks + a_csel;
            uint32_t pa[4];
            ldsm_x4(pa[0], pa[1], pa[2], pa[3],
                    sPt + pr * 256 + ((pch ^ (pr & 7)) << 4));
#pragma unroll
            for (int dd = 0; dd < 8; dd++) {
                const int r = 16 * dd + b_row;
                const int cc = 2 * ks + b_sub;
                uint32_t vb0, vb1, vb2, vb3;
                ldsm_x4(vb0, vb1, vb2, vb3, sVt + r * 256 + ((cc ^ (r & 7)) << 4));
                mma_tf32a(o[2 * dd + 0], pa, vb0, vb1);
                mma_tf32a(o[2 * dd + 1], pa, vb2, vb3);
            }
        }
    }

    // epilogue: quad-reduce l, normalize, store tf32-rounded
    l0 += __shfl_xor_sync(0xffffffffu, l0, 1);
    l0 += __shfl_xor_sync(0xffffffffu, l0, 2);
    l1 += __shfl_xor_sync(0xffffffffu, l1, 1);
    l1 += __shfl_xor_sync(0xffffffffu, l1, 2);
    const float i0 = 1.f / l0, i1 = 1.f / l1;

    float* O0 = O + ((size_t)(b * TT) + r0) * QDIM + h * HD;
    float* O1 = O + ((size_t)(b * TT) + r1) * QDIM + h * HD;
#pragma unroll
    for (int dd = 0; dd < 16; dd++) {
        *(float2*)(O0 + 8 * dd + 2 * q4) =
            make_float2(f2tff(o[dd][0] * i0), f2tff(o[dd][1] * i0));
        *(float2*)(O1 + 8 * dd + 2 * q4) =
            make_float2(f2tff(o[dd][2] * i1), f2tff(o[dd][3] * i1));
    }

    // release: this (128-row q-block, head) is complete
    __threadfence();
    __syncthreads();
    if (tid == 0) atomicAdd(&g_at_done[(b << 4) + (qm >> 7)], 1);
}

// ---------------------------------------------------------------------------

extern "C" void kernel_launch(void* const* d_in, const int* in_sizes, int n_in,
                              void* d_out, int out_size)
{
    const float* x   = (const float*)d_in[0];
    const float* wq  = (const float*)d_in[1];
    const float* wkv = (const float*)d_in[2];
    const float* wo  = (const float*)d_in[3];
    float* out = (float*)d_out;

    float *Qb, *Ob, *xt, *wqt, *wkvt, *wot;
    cudaGetSymbolAddress((void**)&Qb,   g_Q);
    cudaGetSymbolAddress((void**)&Ob,   g_O);
    cudaGetSymbolAddress((void**)&xt,   g_xt);
    cudaGetSymbolAddress((void**)&wqt,  g_wqt);
    cudaGetSymbolAddress((void**)&wkvt, g_wkvt);
    cudaGetSymbolAddress((void**)&wot,  g_wot);

    cudaFuncSetAttribute(gemm_qkv, cudaFuncAttributeMaxDynamicSharedMemorySize, GEMM_SMEM);
    cudaFuncSetAttribute(gemm_o,   cudaFuncAttributeMaxDynamicSharedMemorySize, GEMM_SMEM);
    cudaFuncSetAttribute(attn_mma, cudaFuncAttributeMaxDynamicSharedMemorySize, ATTN_SMEM);

    // 1. fused pre-rounding + flag reset
    cvt_all<<<(N4 + 255) / 256, 256>>>((const float4*)x, (const float4*)wq,
                                       (const float4*)wkv, (const float4*)wo);

    // 2. fused Q + KV projection (plain launch; triggers PDL completion early)
    gemm_qkv<<<dim3(QDIM/128 + KVDIM/128, MTOT/128), 256, GEMM_SMEM>>>(xt, wqt, wkvt);

    // 3. attention — PDL consumer of gemm_qkv, gated by g_kv_done flags
    {
        cudaLaunchAttribute at[1];
        at[0].id = cudaLaunchAttributeProgrammaticStreamSerialization;
        at[0].val.programmaticStreamSerializationAllowed = 1;
        cudaLaunchConfig_t cfg = {};
        cfg.gridDim  = dim3(TT / 128, BB * NH);
        cfg.blockDim = dim3(256);
        cfg.dynamicSmemBytes = ATTN_SMEM;
        cfg.stream = 0;
        cfg.attrs = at;
        cfg.numAttrs = 1;
        cudaLaunchKernelEx(&cfg, attn_mma, (const float*)Qb, Ob);
    }

    // 4. output projection — PDL consumer of attn, gated by g_at_done flags
    {
        cudaLaunchAttribute at[1];
        at[0].id = cudaLaunchAttributeProgrammaticStreamSerialization;
        at[0].val.programmaticStreamSerializationAllowed = 1;
        cudaLaunchConfig_t cfg = {};
        cfg.gridDim  = dim3(QDIM / 128, MTOT / 128);
        cfg.blockDim = dim3(256);
        cfg.dynamicSmemBytes = GEMM_SMEM;
        cfg.stream = 0;
        cfg.attrs = at;
        cfg.numAttrs = 1;
        cudaLaunchKernelEx(&cfg, gemm_o, (const float*)Ob, (const float*)wot, out);
    }
}

// round 16
// speedup vs baseline: 1.2563x; 1.2563x over previous
#include <cuda_runtime.h>
#include <cstdint>
#include <math.h>

#define HIDDEN 2048
#define NH 16
#define NKV 4
#define HD 128
#define BB 2
#define TT 2048
#define MTOT (BB*TT)            // 4096 rows (B*T)
#define QDIM (NH*HD)            // 2048
#define KVDIM (2*NKV*HD)        // 1024

// Scratch (allocation-free)
__device__ float g_Q  [MTOT * QDIM];            // Q proj out: pre-scaled, tf32-rounded
__device__ float g_K2 [BB * NKV * TT * HD];     // K: [b][kvh][t][d], tf32-rounded
__device__ float g_Vt [BB * NKV * HD * TT];     // V^T: [b][kvh][d][t], tf32-rounded
__device__ float g_O  [MTOT * QDIM];            // attention out, tf32-rounded
__device__ float g_xt [MTOT * HIDDEN];          // tf32-rounded inputs
__device__ float g_wqt [QDIM * HIDDEN];
__device__ float g_wkvt[KVDIM * HIDDEN];
__device__ float g_wot [HIDDEN * QDIM];

// Cross-kernel progress flags (reset each launch by cvt_all)
__device__ int g_kv_done[32];   // per 128-row block of QKV proj output; target 24
__device__ int g_at_done[64];   // per 64-row attention q-tile (global); target 16

__device__ __forceinline__ uint32_t f2tf(float f) {
    uint32_t u;
    asm("cvt.rna.tf32.f32 %0, %1;" : "=r"(u) : "f"(f));
    return u;
}
__device__ __forceinline__ float f2tff(float f) { return __uint_as_float(f2tf(f)); }

__device__ __forceinline__ void cp16(uint32_t smaddr, const void* g) {
    asm volatile("cp.async.cg.shared.global [%0], [%1], 16;" :: "r"(smaddr), "l"(g));
}
#define CP_COMMIT() asm volatile("cp.async.commit_group;" ::: "memory")

__device__ __forceinline__ uint32_t smem_u32(const void* p) {
    return (uint32_t)__cvta_generic_to_shared(p);
}

__device__ __forceinline__ void ldsm_x4(uint32_t& r0, uint32_t& r1, uint32_t& r2, uint32_t& r3,
                                        uint32_t addr) {
    asm volatile("ldmatrix.sync.aligned.m8n8.x4.shared.b16 {%0,%1,%2,%3}, [%4];"
                 : "=r"(r0), "=r"(r1), "=r"(r2), "=r"(r3) : "r"(addr));
}

__device__ __forceinline__ void mma_tf32(float& d0, float& d1, float& d2, float& d3,
                                         uint32_t a0, uint32_t a1, uint32_t a2, uint32_t a3,
                                         uint32_t b0, uint32_t b1) {
    asm volatile("mma.sync.aligned.m16n8k8.row.col.f32.tf32.tf32.f32 "
                 "{%0,%1,%2,%3}, {%4,%5,%6,%7}, {%8,%9}, {%0,%1,%2,%3};"
                 : "+f"(d0), "+f"(d1), "+f"(d2), "+f"(d3)
                 : "r"(a0), "r"(a1), "r"(a2), "r"(a3), "r"(b0), "r"(b1));
}
__device__ __forceinline__ void mma_tf32a(float* d, const uint32_t* a, uint32_t b0, uint32_t b1) {
    mma_tf32(d[0], d[1], d[2], d[3], a[0], a[1], a[2], a[3], b0, b1);
}

// ---------------------------------------------------------------------------
// Fused tf32-rounding pass over all four inputs + flag reset
// ---------------------------------------------------------------------------
#define N1 (MTOT*HIDDEN/4)
#define N2 (N1 + QDIM*HIDDEN/4)
#define N3 (N2 + KVDIM*HIDDEN/4)
#define N4 (N3 + HIDDEN*QDIM/4)

__global__ void cvt_all(const float4* __restrict__ x,  const float4* __restrict__ wq,
                        const float4* __restrict__ wkv, const float4* __restrict__ wo)
{
    const int i = blockIdx.x * blockDim.x + threadIdx.x;
    if (i < 32) g_kv_done[i] = 0;
    if (i < 64) g_at_done[i] = 0;

    const float4* src; float4* dst; int j;
    if (i < N1)      { src = x;   dst = (float4*)g_xt;   j = i; }
    else if (i < N2) { src = wq;  dst = (float4*)g_wqt;  j = i - N1; }
    else if (i < N3) { src = wkv; dst = (float4*)g_wkvt; j = i - N2; }
    else if (i < N4) { src = wo;  dst = (float4*)g_wot;  j = i - N3; }
    else return;
    float4 v = src[j];
    dst[j] = make_float4(f2tff(v.x), f2tff(v.y), f2tff(v.z), f2tff(v.w));
}

// ---------------------------------------------------------------------------
// TF32 mma.sync GEMM with cp.async pipeline.
// mode 0: plain fp32 store to C
// mode 1: Q — store f2tf(scale * v) to C (=g_Q)
// mode 2: KV — scatter K to g_K2 [b][kvh][t][d], V to g_Vt [b][kvh][d][t], tf32
// ---------------------------------------------------------------------------
#define LDA 20
#define NSTAGE 4
#define STG_W (128 * LDA)
#define GEMM_SMEM (NSTAGE * 2 * STG_W * 4)   // 81920 B

__device__ __forceinline__ void epi_kv(int rg, int col, float x, float y)
{
    const int b = rg >> 11, t = rg & (TT - 1);
    if (col < NKV * HD) {
        const int kvh = col >> 7, d = col & 127;
        *(float2*)(g_K2 + ((size_t)((b * NKV + kvh) * TT + t)) * HD + d) =
            make_float2(f2tff(x), f2tff(y));
    } else {
        const int c2 = col - NKV * HD;
        const int kvh = c2 >> 7, d = c2 & 127;
        float* base = g_Vt + ((size_t)(b * NKV + kvh) * HD + d) * TT + t;
        base[0]  = f2tff(x);
        base[TT] = f2tff(y);
    }
}

__device__ __forceinline__ void gemm_core(const float* __restrict__ A,
                                          const float* __restrict__ B,
                                          float* __restrict__ C,
                                          int bm, int bn, int N, int K, int mode)
{
    extern __shared__ uint32_t smg[];
    uint32_t* sA = smg;
    uint32_t* sB = smg + NSTAGE * STG_W;

    const int tid  = threadIdx.x;
    const int lane = tid & 31;
    const int wid  = tid >> 5;
    const int wm   = wid & 1;
    const int wn   = wid >> 1;

    const int grow  = tid >> 2;
    const int gcol4 = tid & 3;

    const int gA = lane >> 3;
    const int a_row   = (lane & 7) | ((gA & 1) << 3);
    const int a_chunk = (gA >> 1) * 4;
    const int b_row   = (lane & 7) | (((lane >> 3) >> 1) << 3);
    const int b_chunk = ((lane >> 3) & 1) * 4;

    const uint32_t sAb = smem_u32(sA);
    const uint32_t sBb = smem_u32(sB);

    const float* Ar = A + (size_t)(bm + grow) * K + gcol4 * 4;
    const float* Br = B + (size_t)(bn + grow) * K + gcol4 * 4;
    const uint32_t doff = 4u * (grow * LDA + gcol4 * 4);

    float c[4][4][4];
#pragma unroll
    for (int mi = 0; mi < 4; mi++)
#pragma unroll
        for (int ni = 0; ni < 4; ni++)
#pragma unroll
            for (int r = 0; r < 4; r++) c[mi][ni][r] = 0.f;

    const int NKT = K / 16;

    auto issue = [&](int kt) {
        const int s = kt & (NSTAGE - 1);
        const uint32_t sb = 4u * (s * STG_W);
        const int koff = kt * 16;
        cp16(sAb + sb + doff,                 Ar + koff);
        cp16(sAb + sb + doff + 4u * 64 * LDA, Ar + koff + (size_t)64 * K);
        cp16(sBb + sb + doff,                 Br + koff);
        cp16(sBb + sb + doff + 4u * 64 * LDA, Br + koff + (size_t)64 * K);
    };

    issue(0); CP_COMMIT();
    issue(1); CP_COMMIT();
    issue(2); CP_COMMIT();

    for (int kt = 0; kt < NKT; kt++) {
        asm volatile("cp.async.wait_group 2;" ::: "memory");
        __syncthreads();

        if (kt + 3 < NKT) issue(kt + 3);
        CP_COMMIT();

        const int cur = kt & (NSTAGE - 1);
        const uint32_t baseA = sAb + 4u * (cur * STG_W);
        const uint32_t baseB = sBb + 4u * (cur * STG_W);
#pragma unroll
        for (int ks = 0; ks < 2; ks++) {
            uint32_t a[4][4];
#pragma unroll
            for (int mi = 0; mi < 4; mi++) {
                uint32_t addr = baseA + 4u * ((wm * 64 + mi * 16 + a_row) * LDA + ks * 8 + a_chunk);
                ldsm_x4(a[mi][0], a[mi][1], a[mi][2], a[mi][3], addr);
            }
            uint32_t b[2][4];
#pragma unroll
            for (int p = 0; p < 2; p++) {
                uint32_t addr = baseB + 4u * ((wn * 32 + p * 16 + b_row) * LDA + ks * 8 + b_chunk);
                ldsm_x4(b[p][0], b[p][1], b[p][2], b[p][3], addr);
            }
#pragma unroll
            for (int mi = 0; mi < 4; mi++) {
#pragma unroll
                for (int p = 0; p < 2; p++) {
                    mma_tf32a(c[mi][2*p+0], a[mi], b[p][0], b[p][1]);
                    mma_tf32a(c[mi][2*p+1], a[mi], b[p][2], b[p][3]);
                }
            }
        }
    }

    const float qscale = 0.08838834764831845f;   // 1/sqrt(128)
#pragma unroll
    for (int mi = 0; mi < 4; mi++) {
        int rg = bm + wm * 64 + mi * 16 + (lane >> 2);
#pragma unroll
        for (int ni = 0; ni < 4; ni++) {
            int col = bn + wn * 32 + ni * 8 + (lane & 3) * 2;
            if (mode == 0) {
                *(float2*)(C + (size_t)rg * N + col)       = make_float2(c[mi][ni][0], c[mi][ni][1]);
                *(float2*)(C + (size_t)(rg + 8) * N + col) = make_float2(c[mi][ni][2], c[mi][ni][3]);
            } else if (mode == 1) {
                *(float2*)(C + (size_t)rg * N + col) =
                    make_float2(f2tff(qscale * c[mi][ni][0]), f2tff(qscale * c[mi][ni][1]));
                *(float2*)(C + (size_t)(rg + 8) * N + col) =
                    make_float2(f2tff(qscale * c[mi][ni][2]), f2tff(qscale * c[mi][ni][3]));
            } else {
                epi_kv(rg,     col, c[mi][ni][0], c[mi][ni][1]);
                epi_kv(rg + 8, col, c[mi][ni][2], c[mi][ni][3]);
            }
        }
    }
}

__global__ __launch_bounds__(256, 2) void gemm_qkv(const float* __restrict__ xt,
                                                   const float* __restrict__ wqt,
                                                   const float* __restrict__ wkvt)
{
#if __CUDA_ARCH__ >= 900
    cudaTriggerProgrammaticLaunchCompletion();
#endif
    // Interleave row blocks across batches: byr 0,1,2,3,... -> by 0,16,1,17,...
    // so both batches' early row-blocks complete in the first wave.
    const int byr = blockIdx.y;
    const int by  = (byr & 1) ? (16 + (byr >> 1)) : (byr >> 1);
    const int bx  = blockIdx.x;
    const int bm  = by * 128;
    if (bx < QDIM / 128)
        gemm_core(xt, wqt, g_Q, bm, bx * 128, QDIM, HIDDEN, 1);
    else
        gemm_core(xt, wkvt, nullptr, bm, (bx - QDIM / 128) * 128, KVDIM, HIDDEN, 2);

    // release: this (bm, bn-tile) is complete
    __threadfence();
    __syncthreads();
    if (threadIdx.x == 0) atomicAdd(&g_kv_done[by], 1);
}

__global__ __launch_bounds__(256, 2) void gemm_o(const float* __restrict__ A,
                                                 const float* __restrict__ B,
                                                 float* __restrict__ C)
{
    // acquire: need attention q-tiles 2*by and 2*by+1 complete (16 heads each)
    if (threadIdx.x == 0) {
        const int q0 = blockIdx.y * 2;
        while (((volatile int*)g_at_done)[q0]     < 16) __nanosleep(64);
        while (((volatile int*)g_at_done)[q0 + 1] < 16) __nanosleep(64);
    }
    __syncthreads();
    gemm_core(A, B, C, blockIdx.y * 128, blockIdx.x * 128, QDIM, HIDDEN, 0);
}

// ---------------------------------------------------------------------------
// Flash attention (causal, GQA), tf32 mma.sync, fully cp.async-fed (R13 body).
// K double-buffered; V^T single-buffered, wait deferred past softmax;
// P via smem (272B rows). Grid axes: x = head (bh), y = q-tile (ascending) so
// the first scheduling wave spans ALL heads at LOW q-tiles (matches producer).
// ---------------------------------------------------------------------------
#define K_STAGE_B 32768                 // 64 keys x 512B
#define VT_B      32768                 // 128 d x 256B
#define P_STR     68                    // words; 272B rows (16B multiple, 272/16=17 odd)
#define P_B       (64 * P_STR * 4)      // 17408
#define ATTN_SMEM (2 * K_STAGE_B + VT_B + P_B)   // 115712

__global__ __launch_bounds__(128, 2) void attn_mma(const float* __restrict__ Q,
                                                   float* __restrict__ O)
{
#if __CUDA_ARCH__ >= 900
    cudaTriggerProgrammaticLaunchCompletion();
#endif
    extern __shared__ uint8_t smb[];
    const uint32_t sK0 = smem_u32(smb);
    const uint32_t sVt = sK0 + 2 * K_STAGE_B;
    const uint32_t sP  = sVt + VT_B;
    uint32_t* Pg = (uint32_t*)(smb + 2 * K_STAGE_B + VT_B);

    const int bh  = blockIdx.x;               // head-major: first wave = all heads
    const int b   = bh / NH;
    const int h   = bh % NH;
    const int kvh = h / (NH / NKV);
    const int qm  = blockIdx.y * 64;          // ascending q-tiles

    const int tid  = threadIdx.x;
    const int w    = tid >> 5;
    const int lane = tid & 31;
    const int g    = lane >> 3;
    const int q4   = lane & 3;
    const int hr   = lane >> 2;
    const int a_row   = (lane & 7) | ((g & 1) << 3);
    const int a_chunk = (g >> 1) * 4;               // words
    const int b_row   = (lane & 7) | ((g >> 1) << 3);
    const int b_sub   = (g & 1);                    // 16B sub-chunk within k-step

    // acquire: need QKV row-blocks b*16 .. b*16 + (qm+63)/128 complete
    if (tid == 0) {
        const int kb_hi = b * 16 + ((qm + 63) >> 7);
        for (int kb = b * 16; kb <= kb_hi; kb++)
            while (((volatile int*)g_kv_done)[kb] < 24) __nanosleep(64);
    }
    __syncthreads();

    const int r0 = qm + 16 * w + hr;
    const int r1 = r0 + 8;

    const float* Kg = g_K2 + (size_t)(b * NKV + kvh) * TT * HD;
    const float* Vg = g_Vt + (size_t)(b * NKV + kvh) * HD * TT;

    // cp.async fill mappings
    const int kr = tid >> 5;   // K: rows kr+4j, chunk kc (32 per 512B row)
    const int kc = tid & 31;
    const int vd = tid >> 4;   // V: d-rows vd+8j, chunk vc (16 per 256B row)
    const int vc = tid & 15;

    auto fill_K = [&](int t, int stage) {
        const uint32_t dstb = sK0 + stage * K_STAGE_B;
        const float* src = Kg + (size_t)(t * 64 + kr) * HD + kc * 4;
#pragma unroll
        for (int j = 0; j < 16; j++) {
            const int r = kr + 4 * j;
            cp16(dstb + r * 512 + ((kc ^ (r & 7)) << 4), src + (size_t)(4 * j) * HD);
        }
    };
    auto fill_V = [&](int t) {
        const float* src = Vg + (size_t)vd * TT + t * 64 + vc * 4;
#pragma unroll
        for (int j = 0; j < 16; j++) {
            const int d = vd + 8 * j;
            cp16(sVt + d * 256 + ((vc ^ (d & 7)) << 4), src + (size_t)(8 * j) * TT);
        }
    };

    // prefetch K tile 0, then load Q fragments (pre-scaled, pre-rounded)
    fill_K(0, 0);
    CP_COMMIT();

    uint32_t qf[16][4];
    {
        const uint32_t* Q0 = (const uint32_t*)(Q + ((size_t)(b * TT) + r0) * QDIM + h * HD);
        const uint32_t* Q1 = (const uint32_t*)(Q + ((size_t)(b * TT) + r1) * QDIM + h * HD);
#pragma unroll
        for (int ks = 0; ks < 16; ks++) {
            qf[ks][0] = Q0[8 * ks + q4];
            qf[ks][1] = Q1[8 * ks + q4];
            qf[ks][2] = Q0[8 * ks + q4 + 4];
            qf[ks][3] = Q1[8 * ks + q4 + 4];
        }
    }

    float o[16][4];
#pragma unroll
    for (int i = 0; i < 16; i++)
#pragma unroll
        for (int r = 0; r < 4; r++) o[i][r] = 0.f;
    float m0 = -INFINITY, m1 = -INFINITY, l0 = 0.f, l1 = 0.f;

    const int ntiles = qm / 64 + 1;
    for (int t = 0; t < ntiles; t++) {
        const int n0 = t * 64;
        __syncthreads();                       // all warps done reading old V / K stage

        fill_V(t);
        CP_COMMIT();                           // group V(t)
        if (t + 1 < ntiles) fill_K(t + 1, (t + 1) & 1);
        CP_COMMIT();                           // group K(t+1) (possibly empty)

        asm volatile("cp.async.wait_group 2;" ::: "memory");   // K(t) arrived
        __syncthreads();

        // S = Q K^T
        const uint32_t sKst = sK0 + (t & 1) * K_STAGE_B;
        float s[8][4];
#pragma unroll
        for (int j = 0; j < 8; j++)
#pragma unroll
            for (int r = 0; r < 4; r++) s[j][r] = 0.f;
#pragma unroll
        for (int ks = 0; ks < 16; ks++) {
            uint32_t kb[4][4];
#pragma unroll
            for (int jj = 0; jj < 4; jj++) {
                const int r = 16 * jj + b_row;
                const int cc = 2 * ks + b_sub;
                ldsm_x4(kb[jj][0], kb[jj][1], kb[jj][2], kb[jj][3],
                        sKst + r * 512 + ((cc ^ (r & 7)) << 4));
            }
#pragma unroll
            for (int jj = 0; jj < 4; jj++) {
                mma_tf32a(s[2 * jj + 0], qf[ks], kb[jj][0], kb[jj][1]);
                mma_tf32a(s[2 * jj + 1], qf[ks], kb[jj][2], kb[jj][3]);
            }
        }

        // causal mask + online softmax
        float mt0 = -INFINITY, mt1 = -INFINITY;
#pragma unroll
        for (int j = 0; j < 8; j++) {
            const int c0 = n0 + 8 * j + 2 * q4, c1 = c0 + 1;
            if (c0 > r0) s[j][0] = -1e30f;
            if (c1 > r0) s[j][1] = -1e30f;
            if (c0 > r1) s[j][2] = -1e30f;
            if (c1 > r1) s[j][3] = -1e30f;
            mt0 = fmaxf(mt0, fmaxf(s[j][0], s[j][1]));
            mt1 = fmaxf(mt1, fmaxf(s[j][2], s[j][3]));
        }
        mt0 = fmaxf(mt0, __shfl_xor_sync(0xffffffffu, mt0, 1));
        mt0 = fmaxf(mt0, __shfl_xor_sync(0xffffffffu, mt0, 2));
        mt1 = fmaxf(mt1, __shfl_xor_sync(0xffffffffu, mt1, 1));
        mt1 = fmaxf(mt1, __shfl_xor_sync(0xffffffffu, mt1, 2));
        const float mn0 = fmaxf(m0, mt0), mn1 = fmaxf(m1, mt1);
        const float al0 = __expf(m0 - mn0), al1 = __expf(m1 - mn1);
        m0 = mn0; m1 = mn1;
        float ls0 = 0.f, ls1 = 0.f;
#pragma unroll
        for (int j = 0; j < 8; j++) {
            s[j][0] = __expf(s[j][0] - mn0); ls0 += s[j][0];
            s[j][1] = __expf(s[j][1] - mn0); ls0 += s[j][1];
            s[j][2] = __expf(s[j][2] - mn1); ls1 += s[j][2];
            s[j][3] = __expf(s[j][3] - mn1); ls1 += s[j][3];
        }
        l0 = l0 * al0 + ls0;
        l1 = l1 * al1 + ls1;
#pragma unroll
        for (int i = 0; i < 16; i++) {
            o[i][0] *= al0; o[i][1] *= al0;
            o[i][2] *= al1; o[i][3] *= al1;
        }

        // P (tf32) -> smem; warp reads back only its own 16 rows
        const int prow = 16 * w + hr;
#pragma unroll
        for (int j = 0; j < 8; j++) {
            *(uint2*)(Pg + prow * P_STR + 8 * j + 2 * q4)       =
                make_uint2(f2tf(s[j][0]), f2tf(s[j][1]));
            *(uint2*)(Pg + (prow + 8) * P_STR + 8 * j + 2 * q4) =
                make_uint2(f2tf(s[j][2]), f2tf(s[j][3]));
        }
        __syncwarp();

        asm volatile("cp.async.wait_group 1;" ::: "memory");   // V(t) arrived
        __syncthreads();

        // O += P V  (A-frags from P smem, B-frags from V^T smem)
#pragma unroll
        for (int ks = 0; ks < 8; ks++) {
            uint32_t pa[4];
            ldsm_x4(pa[0], pa[1], pa[2], pa[3],
                    sP + 4u * ((16 * w + a_row) * P_STR + 8 * ks + a_chunk));
#pragma unroll
            for (int dd = 0; dd < 8; dd++) {
                const int r = 16 * dd + b_row;
                const int cc = 2 * ks + b_sub;
                uint32_t vb0, vb1, vb2, vb3;
                ldsm_x4(vb0, vb1, vb2, vb3, sVt + r * 256 + ((cc ^ (r & 7)) << 4));
                mma_tf32a(o[2 * dd + 0], pa, vb0, vb1);
                mma_tf32a(o[2 * dd + 1], pa, vb2, vb3);
            }
        }
    }

    // epilogue: quad-reduce l, normalize, store tf32-rounded
    l0 += __shfl_xor_sync(0xffffffffu, l0, 1);
    l0 += __shfl_xor_sync(0xffffffffu, l0, 2);
    l1 += __shfl_xor_sync(0xffffffffu, l1, 1);
    l1 += __shfl_xor_sync(0xffffffffu, l1, 2);
    const float i0 = 1.f / l0, i1 = 1.f / l1;

    float* O0 = O + ((size_t)(b * TT) + r0) * QDIM + h * HD;
    float* O1 = O + ((size_t)(b * TT) + r1) * QDIM + h * HD;
#pragma unroll
    for (int dd = 0; dd < 16; dd++) {
        *(float2*)(O0 + 8 * dd + 2 * q4) =
            make_float2(f2tff(o[dd][0] * i0), f2tff(o[dd][1] * i0));
        *(float2*)(O1 + 8 * dd + 2 * q4) =
            make_float2(f2tff(o[dd][2] * i1), f2tff(o[dd][3] * i1));
    }

    // release: this (qtile, head) is complete
    __threadfence();
    __syncthreads();
    if (tid == 0) atomicAdd(&g_at_done[(b << 5) + (qm >> 6)], 1);
}

// ---------------------------------------------------------------------------

extern "C" void kernel_launch(void* const* d_in, const int* in_sizes, int n_in,
                              void* d_out, int out_size)
{
    const float* x   = (const float*)d_in[0];
    const float* wq  = (const float*)d_in[1];
    const float* wkv = (const float*)d_in[2];
    const float* wo  = (const float*)d_in[3];
    float* out = (float*)d_out;

    float *Qb, *Ob, *xt, *wqt, *wkvt, *wot;
    cudaGetSymbolAddress((void**)&Qb,   g_Q);
    cudaGetSymbolAddress((void**)&Ob,   g_O);
    cudaGetSymbolAddress((void**)&xt,   g_xt);
    cudaGetSymbolAddress((void**)&wqt,  g_wqt);
    cudaGetSymbolAddress((void**)&wkvt, g_wkvt);
    cudaGetSymbolAddress((void**)&wot,  g_wot);

    cudaFuncSetAttribute(gemm_qkv, cudaFuncAttributeMaxDynamicSharedMemorySize, GEMM_SMEM);
    cudaFuncSetAttribute(gemm_o,   cudaFuncAttributeMaxDynamicSharedMemorySize, GEMM_SMEM);
    cudaFuncSetAttribute(attn_mma, cudaFuncAttributeMaxDynamicSharedMemorySize, ATTN_SMEM);

    // 1. fused pre-rounding + flag reset
    cvt_all<<<(N4 + 255) / 256, 256>>>((const float4*)x, (const float4*)wq,
                                       (const float4*)wkv, (const float4*)wo);

    // 2. fused Q + KV projection (batch-interleaved row order)
    gemm_qkv<<<dim3(QDIM/128 + KVDIM/128, MTOT/128), 256, GEMM_SMEM>>>(xt, wqt, wkvt);

    // 3. attention — PDL consumer of gemm_qkv, gated by g_kv_done flags
    //    grid: x = heads (64), y = q-tiles (32, ascending)
    {
        cudaLaunchAttribute at[1];
        at[0].id = cudaLaunchAttributeProgrammaticStreamSerialization;
        at[0].val.programmaticStreamSerializationAllowed = 1;
        cudaLaunchConfig_t cfg = {};
        cfg.gridDim  = dim3(BB * NH, TT / 64);
        cfg.blockDim = dim3(128);
        cfg.dynamicSmemBytes = ATTN_SMEM;
        cfg.stream = 0;
        cfg.attrs = at;
        cfg.numAttrs = 1;
        cudaLaunchKernelEx(&cfg, attn_mma, (const float*)Qb, Ob);
    }

    // 4. output projection — PDL consumer of attn, gated by g_at_done flags
    {
        cudaLaunchAttribute at[1];
        at[0].id = cudaLaunchAttributeProgrammaticStreamSerialization;
        at[0].val.programmaticStreamSerializationAllowed = 1;
        cudaLaunchConfig_t cfg = {};
        cfg.gridDim  = dim3(QDIM / 128, MTOT / 128);
        cfg.blockDim = dim3(256);
        cfg.dynamicSmemBytes = GEMM_SMEM;
        cfg.stream = 0;
        cfg.attrs = at;
        cfg.numAttrs = 1;
        cudaLaunchKernelEx(&cfg, gemm_o, (const float*)Ob, (const float*)wot, out);
    }
}